// round 7
// baseline (speedup 1.0000x reference)
#include <cuda_runtime.h>
#include <cstdint>

#define N_NODES 50000
#define N_EDGES 800000
#define NB_SCAN 196          // ceil(50000/256)

// ---------------- device scratch (allocation-free rule: __device__ globals) ----
__device__ __align__(16) float g_dinv[N_NODES];
__device__ __align__(16) float g_h  [N_NODES * 64];   // GEMM output of current layer
__device__ __align__(16) float g_x1 [N_NODES * 64];   // layer-1 activation
__device__ __align__(16) float g_x2 [N_NODES * 64];   // layer-2 activation
__device__ int   g_deg [N_NODES];
__device__ int   g_ptr [N_NODES + 1];
__device__ int   g_fill[N_NODES];
__device__ int   g_bsum[NB_SCAN];
__device__ int   g_csr_src[N_EDGES];
__device__ float g_csr_w  [N_EDGES];

// ---------------- degree histogram (4 edges/thread for MLP) ---------------------
__global__ void k_count_deg(const int* __restrict__ ei, int* deg) {
    int base   = blockIdx.x * blockDim.x + threadIdx.x;
    int stride = gridDim.x * blockDim.x;
#pragma unroll
    for (int k = 0; k < 4; k++) {
        int e = base + k * stride;
        if (e < N_EDGES) atomicAdd(&deg[ei[N_EDGES + e]], 1);
    }
}

// ---------------- scanA: per-block sums of deg ----------------------------------
__global__ void k_scanA(const int* __restrict__ deg, int* __restrict__ bsum) {
    __shared__ int s[256];
    int t = threadIdx.x;
    int i = blockIdx.x * 256 + t;
    s[t] = (i < N_NODES) ? deg[i] : 0;
    __syncthreads();
    for (int o = 128; o > 0; o >>= 1) {
        if (t < o) s[t] += s[t + o];
        __syncthreads();
    }
    if (t == 0) bsum[blockIdx.x] = s[0];
}

// ---- scanC: per-node exclusive prefix + dinv; block offset computed inline -----
__global__ void k_scanC(const int* __restrict__ deg, const int* __restrict__ bsum,
                        int* __restrict__ ptr, int* __restrict__ fill,
                        float* __restrict__ dinv) {
    __shared__ int s[256];
    __shared__ int sB[256];
    __shared__ int blockOff;
    int t = threadIdx.x;

    // inline exclusive scan of the 196 block sums (redundant per block, cheap)
    int bv = (t < NB_SCAN) ? bsum[t] : 0;
    sB[t] = bv;
    __syncthreads();
    for (int o = 1; o < 256; o <<= 1) {
        int u = (t >= o) ? sB[t - o] : 0;
        __syncthreads();
        sB[t] += u;
        __syncthreads();
    }
    if (t == blockIdx.x) blockOff = sB[t] - bv;  // exclusive prefix of this block
    __syncthreads();

    // per-node scan within block
    int i = blockIdx.x * 256 + t;
    int v = (i < N_NODES) ? deg[i] : 0;
    s[t] = v;
    __syncthreads();
    for (int o = 1; o < 256; o <<= 1) {
        int u = (t >= o) ? s[t - o] : 0;
        __syncthreads();
        s[t] += u;
        __syncthreads();
    }
    int excl = s[t] - v + blockOff;
    if (i < N_NODES) {
        ptr[i]  = excl;
        fill[i] = excl;
        dinv[i] = rsqrtf((float)v + 1.0f);  // +1 self-loop
    }
    if (i == N_NODES) ptr[N_NODES] = N_EDGES;
}

// ---------------- counting-sort fill (4 edges/thread for MLP) -------------------
__global__ void k_fill(const int* __restrict__ ei, const float* __restrict__ dinv,
                       int* fill, int* __restrict__ csr_src, float* __restrict__ csr_w) {
    int base   = blockIdx.x * blockDim.x + threadIdx.x;
    int stride = gridDim.x * blockDim.x;
#pragma unroll
    for (int k = 0; k < 4; k++) {
        int e = base + k * stride;
        if (e < N_EDGES) {
            int s = ei[e];
            int d = ei[N_EDGES + e];
            int pos = atomicAdd(&fill[d], 1);
            csr_src[pos] = s;
            csr_w[pos]   = dinv[s] * dinv[d];
        }
    }
}

// ---------------- small GEMM: H[N, DOUT] = X[N, 64] @ W[64, DOUT] ---------------
template <int DOUT>
__global__ void k_gemm(const float* __restrict__ X, const float* __restrict__ W,
                       float* __restrict__ H) {
    constexpr int DIN  = 64;
    constexpr int C4   = DOUT / 4;         // float4 cols per row: 16 or 8
    constexpr int ROWS = 256 / C4;         // rows per block: 16 or 32
    constexpr int XS   = 17;               // padded row stride in float4
    __shared__ float4 sW[DIN * C4];        // W as [k][c4]
    __shared__ float4 sX4[ROWS * XS];

    int tid = threadIdx.x;
    for (int i = tid; i < DIN * C4; i += 256)
        sW[i] = ((const float4*)W)[i];

    int rowbase = blockIdx.x * ROWS;
    for (int i = tid; i < ROWS * (DIN / 4); i += 256) {
        int r = i / (DIN / 4);
        int q = i % (DIN / 4);
        int row = rowbase + r;
        sX4[r * XS + q] = (row < N_NODES)
            ? ((const float4*)X)[(size_t)row * (DIN / 4) + q]
            : make_float4(0.f, 0.f, 0.f, 0.f);
    }
    __syncthreads();

    int c4  = tid % C4;
    int r   = tid / C4;
    int row = rowbase + r;
    if (row >= N_NODES) return;

    const float* sx = (const float*)&sX4[r * XS];
    float4 acc = make_float4(0.f, 0.f, 0.f, 0.f);
#pragma unroll
    for (int k = 0; k < DIN; k++) {
        float  xv = sx[k];
        float4 wv = sW[k * C4 + c4];
        acc.x = fmaf(xv, wv.x, acc.x);
        acc.y = fmaf(xv, wv.y, acc.y);
        acc.z = fmaf(xv, wv.z, acc.z);
        acc.w = fmaf(xv, wv.w, acc.w);
    }
    ((float4*)H)[(size_t)row * C4 + c4] = acc;
}

// ---- fused pull aggregation + self-loop + bias + activation --------------------
template <int DOUT, bool TANH>
__global__ void k_agg(const int* __restrict__ ptr, const int* __restrict__ csr_src,
                      const float* __restrict__ csr_w,
                      const float* __restrict__ H, const float* __restrict__ dinv,
                      const float* __restrict__ b, float* __restrict__ OUT) {
    constexpr int C   = DOUT / 4;     // 16 (d=64) or 8 (d=32)
    constexpr int NPB = 256 / C;      // nodes per block
    int lane = threadIdx.x % C;
    int node = blockIdx.x * NPB + threadIdx.x / C;
    if (node >= N_NODES) return;

    int beg = ptr[node];
    int end = ptr[node + 1];
    const float4* H4 = (const float4*)H;

    float4 acc = make_float4(0.f, 0.f, 0.f, 0.f);
    int e = beg;
    for (; e + 3 < end; e += 4) {
        int    s0 = csr_src[e],     s1 = csr_src[e + 1];
        int    s2 = csr_src[e + 2], s3 = csr_src[e + 3];
        float  w0 = csr_w[e],       w1 = csr_w[e + 1];
        float  w2 = csr_w[e + 2],   w3 = csr_w[e + 3];
        float4 v0 = H4[(size_t)s0 * C + lane];
        float4 v1 = H4[(size_t)s1 * C + lane];
        float4 v2 = H4[(size_t)s2 * C + lane];
        float4 v3 = H4[(size_t)s3 * C + lane];
        acc.x += v0.x * w0 + v1.x * w1 + v2.x * w2 + v3.x * w3;
        acc.y += v0.y * w0 + v1.y * w1 + v2.y * w2 + v3.y * w3;
        acc.z += v0.z * w0 + v1.z * w1 + v2.z * w2 + v3.z * w3;
        acc.w += v0.w * w0 + v1.w * w1 + v2.w * w2 + v3.w * w3;
    }
    for (; e < end; e++) {
        int    s0 = csr_src[e];
        float  w0 = csr_w[e];
        float4 v0 = H4[(size_t)s0 * C + lane];
        acc.x += v0.x * w0;
        acc.y += v0.y * w0;
        acc.z += v0.z * w0;
        acc.w += v0.w * w0;
    }

    float di = dinv[node];
    float sl = di * di;                       // self-loop weight
    float4 hh = H4[(size_t)node * C + lane];
    float4 bb = ((const float4*)b)[lane];
    float4 v;
    v.x = acc.x + hh.x * sl + bb.x;
    v.y = acc.y + hh.y * sl + bb.y;
    v.z = acc.z + hh.z * sl + bb.z;
    v.w = acc.w + hh.w * sl + bb.w;
    if (TANH) {
        v.x = tanhf(v.x); v.y = tanhf(v.y); v.z = tanhf(v.z); v.w = tanhf(v.w);
    }
    ((float4*)OUT)[(size_t)node * C + lane] = v;
}

// ---------------- launch --------------------------------------------------------
static inline int cdiv(long long a, int b) { return (int)((a + b - 1) / b); }

extern "C" void kernel_launch(void* const* d_in, const int* in_sizes, int n_in,
                              void* d_out, int out_size) {
    const float* x  = (const float*)d_in[0];
    const int*   ei = (const int*)d_in[1];      // JAX x64 disabled: int64 -> int32
    const float* W1 = (const float*)d_in[2];
    const float* b1 = (const float*)d_in[3];
    const float* W2 = (const float*)d_in[4];
    const float* b2 = (const float*)d_in[5];
    const float* W3 = (const float*)d_in[6];
    const float* b3 = (const float*)d_in[7];
    float*       out = (float*)d_out;

    float *dinv, *h, *x1, *x2, *csr_w;
    int   *deg, *ptr, *fill, *bsum, *csr_src;
    cudaGetSymbolAddress((void**)&dinv,    g_dinv);
    cudaGetSymbolAddress((void**)&h,       g_h);
    cudaGetSymbolAddress((void**)&x1,      g_x1);
    cudaGetSymbolAddress((void**)&x2,      g_x2);
    cudaGetSymbolAddress((void**)&deg,     g_deg);
    cudaGetSymbolAddress((void**)&ptr,     g_ptr);
    cudaGetSymbolAddress((void**)&fill,    g_fill);
    cudaGetSymbolAddress((void**)&bsum,    g_bsum);
    cudaGetSymbolAddress((void**)&csr_src, g_csr_src);
    cudaGetSymbolAddress((void**)&csr_w,   g_csr_w);

    const int T = 256;

    // ---- CSR build + norm ----
    cudaMemsetAsync(deg, 0, N_NODES * sizeof(int));
    k_count_deg<<<cdiv(N_EDGES, T * 4), T>>>(ei, deg);
    k_scanA    <<<NB_SCAN, T>>>(deg, bsum);
    k_scanC    <<<NB_SCAN, T>>>(deg, bsum, ptr, fill, dinv);
    k_fill     <<<cdiv(N_EDGES, T * 4), T>>>(ei, dinv, fill, csr_src, csr_w);

    // ---- layer 1: x -> x1 (tanh) ----
    k_gemm<64><<<cdiv(N_NODES, 16), T>>>(x, W1, h);
    k_agg<64, true><<<cdiv(N_NODES * 16, T), T>>>(ptr, csr_src, csr_w, h, dinv, b1, x1);

    // ---- layer 2: x1 -> x2 (tanh) ----
    k_gemm<64><<<cdiv(N_NODES, 16), T>>>(x1, W2, h);
    k_agg<64, true><<<cdiv(N_NODES * 16, T), T>>>(ptr, csr_src, csr_w, h, dinv, b2, x2);

    // ---- layer 3: x2 -> out (linear) ----
    k_gemm<32><<<cdiv(N_NODES, 32), T>>>(x2, W3, h);
    k_agg<32, false><<<cdiv(N_NODES * 8, T), T>>>(ptr, csr_src, csr_w, h, dinv, b3, out);
}

// round 8
// speedup vs baseline: 1.0665x; 1.0665x over previous
#include <cuda_runtime.h>
#include <cstdint>

#define N_NODES 50000
#define N_EDGES 800000
#define NB_SCAN 196          // ceil(50000/256)

// ---------------- device scratch (allocation-free rule: __device__ globals) ----
__device__ __align__(16) float g_dinv[N_NODES];
__device__ __align__(16) float g_h  [N_NODES * 64];   // GEMM output of current layer
__device__ __align__(16) float g_x1 [N_NODES * 64];   // layer-1 activation
__device__ __align__(16) float g_x2 [N_NODES * 64];   // layer-2 activation
__device__ int   g_deg [N_NODES];
__device__ int   g_ptr [N_NODES + 1];
__device__ int   g_fill[N_NODES];
__device__ int   g_bsum[NB_SCAN];
__device__ int   g_csr_src[N_EDGES];

// ---------------- degree histogram (1 edge/thread: max independent chains) ------
__global__ void k_count_deg(const int* __restrict__ ei, int* deg) {
    int e = blockIdx.x * blockDim.x + threadIdx.x;
    if (e < N_EDGES) atomicAdd(&deg[ei[N_EDGES + e]], 1);
}

// ---------------- scanA: per-block sums of deg ----------------------------------
__global__ void k_scanA(const int* __restrict__ deg, int* __restrict__ bsum) {
    __shared__ int s[256];
    int t = threadIdx.x;
    int i = blockIdx.x * 256 + t;
    s[t] = (i < N_NODES) ? deg[i] : 0;
    __syncthreads();
    for (int o = 128; o > 0; o >>= 1) {
        if (t < o) s[t] += s[t + o];
        __syncthreads();
    }
    if (t == 0) bsum[blockIdx.x] = s[0];
}

// ---- scanC: per-node exclusive prefix + dinv; block offset computed inline -----
__global__ void k_scanC(const int* __restrict__ deg, const int* __restrict__ bsum,
                        int* __restrict__ ptr, int* __restrict__ fill,
                        float* __restrict__ dinv) {
    __shared__ int s[256];
    __shared__ int sB[256];
    __shared__ int blockOff;
    int t = threadIdx.x;

    // inline exclusive scan of the 196 block sums (redundant per block, cheap)
    int bv = (t < NB_SCAN) ? bsum[t] : 0;
    sB[t] = bv;
    __syncthreads();
    for (int o = 1; o < 256; o <<= 1) {
        int u = (t >= o) ? sB[t - o] : 0;
        __syncthreads();
        sB[t] += u;
        __syncthreads();
    }
    if (t == blockIdx.x) blockOff = sB[t] - bv;  // exclusive prefix of this block
    __syncthreads();

    // per-node scan within block
    int i = blockIdx.x * 256 + t;
    int v = (i < N_NODES) ? deg[i] : 0;
    s[t] = v;
    __syncthreads();
    for (int o = 1; o < 256; o <<= 1) {
        int u = (t >= o) ? s[t - o] : 0;
        __syncthreads();
        s[t] += u;
        __syncthreads();
    }
    int excl = s[t] - v + blockOff;
    if (i < N_NODES) {
        ptr[i]  = excl;
        fill[i] = excl;
        dinv[i] = rsqrtf((float)v + 1.0f);  // +1 self-loop
    }
    if (i == N_NODES) ptr[N_NODES] = N_EDGES;
}

// ---------------- counting-sort fill (1 edge/thread; src index only) ------------
__global__ void k_fill(const int* __restrict__ ei, int* fill,
                       int* __restrict__ csr_src) {
    int e = blockIdx.x * blockDim.x + threadIdx.x;
    if (e >= N_EDGES) return;
    int s = ei[e];
    int d = ei[N_EDGES + e];
    int pos = atomicAdd(&fill[d], 1);
    csr_src[pos] = s;
}

// ---------------- small GEMM: H[N, DOUT] = X[N, 64] @ W[64, DOUT] ---------------
template <int DOUT>
__global__ void k_gemm(const float* __restrict__ X, const float* __restrict__ W,
                       float* __restrict__ H) {
    constexpr int DIN  = 64;
    constexpr int C4   = DOUT / 4;         // float4 cols per row: 16 or 8
    constexpr int ROWS = 256 / C4;         // rows per block: 16 or 32
    constexpr int XS   = 17;               // padded row stride in float4
    __shared__ float4 sW[DIN * C4];        // W as [k][c4]
    __shared__ float4 sX4[ROWS * XS];

    int tid = threadIdx.x;
    for (int i = tid; i < DIN * C4; i += 256)
        sW[i] = ((const float4*)W)[i];

    int rowbase = blockIdx.x * ROWS;
    for (int i = tid; i < ROWS * (DIN / 4); i += 256) {
        int r = i / (DIN / 4);
        int q = i % (DIN / 4);
        int row = rowbase + r;
        sX4[r * XS + q] = (row < N_NODES)
            ? ((const float4*)X)[(size_t)row * (DIN / 4) + q]
            : make_float4(0.f, 0.f, 0.f, 0.f);
    }
    __syncthreads();

    int c4  = tid % C4;
    int r   = tid / C4;
    int row = rowbase + r;
    if (row >= N_NODES) return;

    const float* sx = (const float*)&sX4[r * XS];
    float4 acc = make_float4(0.f, 0.f, 0.f, 0.f);
#pragma unroll
    for (int k = 0; k < DIN; k++) {
        float  xv = sx[k];
        float4 wv = sW[k * C4 + c4];
        acc.x = fmaf(xv, wv.x, acc.x);
        acc.y = fmaf(xv, wv.y, acc.y);
        acc.z = fmaf(xv, wv.z, acc.z);
        acc.w = fmaf(xv, wv.w, acc.w);
    }
    ((float4*)H)[(size_t)row * C4 + c4] = acc;
}

// ---- fused pull aggregation + self-loop + bias + activation --------------------
// acc = Σ dinv[s]·h[s];  out = act(dinv[node]·(acc + dinv[node]·h[node]) + b)
template <int DOUT, bool TANH>
__global__ void k_agg(const int* __restrict__ ptr, const int* __restrict__ csr_src,
                      const float* __restrict__ H, const float* __restrict__ dinv,
                      const float* __restrict__ b, float* __restrict__ OUT) {
    constexpr int C   = DOUT / 4;     // 16 (d=64) or 8 (d=32)
    constexpr int NPB = 256 / C;      // nodes per block
    int lane = threadIdx.x % C;
    int node = blockIdx.x * NPB + threadIdx.x / C;
    if (node >= N_NODES) return;

    int beg = ptr[node];
    int end = ptr[node + 1];
    const float4* H4 = (const float4*)H;

    float4 acc = make_float4(0.f, 0.f, 0.f, 0.f);
    int e = beg;
    for (; e + 3 < end; e += 4) {
        int    s0 = csr_src[e],     s1 = csr_src[e + 1];
        int    s2 = csr_src[e + 2], s3 = csr_src[e + 3];
        float  w0 = dinv[s0],       w1 = dinv[s1];
        float  w2 = dinv[s2],       w3 = dinv[s3];
        float4 v0 = H4[(size_t)s0 * C + lane];
        float4 v1 = H4[(size_t)s1 * C + lane];
        float4 v2 = H4[(size_t)s2 * C + lane];
        float4 v3 = H4[(size_t)s3 * C + lane];
        acc.x += v0.x * w0 + v1.x * w1 + v2.x * w2 + v3.x * w3;
        acc.y += v0.y * w0 + v1.y * w1 + v2.y * w2 + v3.y * w3;
        acc.z += v0.z * w0 + v1.z * w1 + v2.z * w2 + v3.z * w3;
        acc.w += v0.w * w0 + v1.w * w1 + v2.w * w2 + v3.w * w3;
    }
    for (; e < end; e++) {
        int    s0 = csr_src[e];
        float  w0 = dinv[s0];
        float4 v0 = H4[(size_t)s0 * C + lane];
        acc.x += v0.x * w0;
        acc.y += v0.y * w0;
        acc.z += v0.z * w0;
        acc.w += v0.w * w0;
    }

    float di = dinv[node];
    float4 hh = H4[(size_t)node * C + lane];
    float4 bb = ((const float4*)b)[lane];
    float4 v;
    v.x = di * (acc.x + di * hh.x) + bb.x;
    v.y = di * (acc.y + di * hh.y) + bb.y;
    v.z = di * (acc.z + di * hh.z) + bb.z;
    v.w = di * (acc.w + di * hh.w) + bb.w;
    if (TANH) {
        v.x = tanhf(v.x); v.y = tanhf(v.y); v.z = tanhf(v.z); v.w = tanhf(v.w);
    }
    ((float4*)OUT)[(size_t)node * C + lane] = v;
}

// ---------------- launch --------------------------------------------------------
static inline int cdiv(long long a, int b) { return (int)((a + b - 1) / b); }

extern "C" void kernel_launch(void* const* d_in, const int* in_sizes, int n_in,
                              void* d_out, int out_size) {
    const float* x  = (const float*)d_in[0];
    const int*   ei = (const int*)d_in[1];      // JAX x64 disabled: int64 -> int32
    const float* W1 = (const float*)d_in[2];
    const float* b1 = (const float*)d_in[3];
    const float* W2 = (const float*)d_in[4];
    const float* b2 = (const float*)d_in[5];
    const float* W3 = (const float*)d_in[6];
    const float* b3 = (const float*)d_in[7];
    float*       out = (float*)d_out;

    float *dinv, *h, *x1, *x2;
    int   *deg, *ptr, *fill, *bsum, *csr_src;
    cudaGetSymbolAddress((void**)&dinv,    g_dinv);
    cudaGetSymbolAddress((void**)&h,       g_h);
    cudaGetSymbolAddress((void**)&x1,      g_x1);
    cudaGetSymbolAddress((void**)&x2,      g_x2);
    cudaGetSymbolAddress((void**)&deg,     g_deg);
    cudaGetSymbolAddress((void**)&ptr,     g_ptr);
    cudaGetSymbolAddress((void**)&fill,    g_fill);
    cudaGetSymbolAddress((void**)&bsum,    g_bsum);
    cudaGetSymbolAddress((void**)&csr_src, g_csr_src);

    const int T = 256;

    // ---- CSR build + norm ----
    cudaMemsetAsync(deg, 0, N_NODES * sizeof(int));
    k_count_deg<<<cdiv(N_EDGES, T), T>>>(ei, deg);
    k_scanA    <<<NB_SCAN, T>>>(deg, bsum);
    k_scanC    <<<NB_SCAN, T>>>(deg, bsum, ptr, fill, dinv);
    k_fill     <<<cdiv(N_EDGES, T), T>>>(ei, fill, csr_src);

    // ---- layer 1: x -> x1 (tanh) ----
    k_gemm<64><<<cdiv(N_NODES, 16), T>>>(x, W1, h);
    k_agg<64, true><<<cdiv(N_NODES * 16, T), T>>>(ptr, csr_src, h, dinv, b1, x1);

    // ---- layer 2: x1 -> x2 (tanh) ----
    k_gemm<64><<<cdiv(N_NODES, 16), T>>>(x1, W2, h);
    k_agg<64, true><<<cdiv(N_NODES * 16, T), T>>>(ptr, csr_src, h, dinv, b2, x2);

    // ---- layer 3: x2 -> out (linear) ----
    k_gemm<32><<<cdiv(N_NODES, 32), T>>>(x2, W3, h);
    k_agg<32, false><<<cdiv(N_NODES * 8, T), T>>>(ptr, csr_src, h, dinv, b3, out);
}

// round 9
// speedup vs baseline: 1.1073x; 1.0383x over previous
#include <cuda_runtime.h>
#include <cuda_fp16.h>
#include <cstdint>

#define N_NODES 50000
#define N_EDGES 800000
#define NB_SCAN 196          // ceil(50000/256)

// ---------------- device scratch (allocation-free rule: __device__ globals) ----
__device__ __align__(16) float  g_dinv[N_NODES];
__device__ __align__(16) __half g_h   [N_NODES * 64];  // GEMM output, fp16 packed
__device__ __align__(16) float  g_x1  [N_NODES * 64];  // layer-1 activation
__device__ __align__(16) float  g_x2  [N_NODES * 64];  // layer-2 activation
__device__ int g_deg [N_NODES];
__device__ int g_ptr [N_NODES + 1];
__device__ int g_fill[N_NODES];
__device__ int g_bsum[NB_SCAN];
__device__ int g_csr_src[N_EDGES];

// ---------------- degree histogram (1 edge/thread: max independent chains) ------
__global__ void k_count_deg(const int* __restrict__ ei, int* deg) {
    int e = blockIdx.x * blockDim.x + threadIdx.x;
    if (e < N_EDGES) atomicAdd(&deg[ei[N_EDGES + e]], 1);
}

// ---------------- scanA: per-block sums of deg ----------------------------------
__global__ void k_scanA(const int* __restrict__ deg, int* __restrict__ bsum) {
    __shared__ int s[256];
    int t = threadIdx.x;
    int i = blockIdx.x * 256 + t;
    s[t] = (i < N_NODES) ? deg[i] : 0;
    __syncthreads();
    for (int o = 128; o > 0; o >>= 1) {
        if (t < o) s[t] += s[t + o];
        __syncthreads();
    }
    if (t == 0) bsum[blockIdx.x] = s[0];
}

// ---- scanC: per-node exclusive prefix + dinv; block offset computed inline -----
__global__ void k_scanC(const int* __restrict__ deg, const int* __restrict__ bsum,
                        int* __restrict__ ptr, int* __restrict__ fill,
                        float* __restrict__ dinv) {
    __shared__ int s[256];
    __shared__ int sB[256];
    __shared__ int blockOff;
    int t = threadIdx.x;

    int bv = (t < NB_SCAN) ? bsum[t] : 0;
    sB[t] = bv;
    __syncthreads();
    for (int o = 1; o < 256; o <<= 1) {
        int u = (t >= o) ? sB[t - o] : 0;
        __syncthreads();
        sB[t] += u;
        __syncthreads();
    }
    if (t == blockIdx.x) blockOff = sB[t] - bv;
    __syncthreads();

    int i = blockIdx.x * 256 + t;
    int v = (i < N_NODES) ? deg[i] : 0;
    s[t] = v;
    __syncthreads();
    for (int o = 1; o < 256; o <<= 1) {
        int u = (t >= o) ? s[t - o] : 0;
        __syncthreads();
        s[t] += u;
        __syncthreads();
    }
    int excl = s[t] - v + blockOff;
    if (i < N_NODES) {
        ptr[i]  = excl;
        fill[i] = excl;
        dinv[i] = rsqrtf((float)v + 1.0f);  // +1 self-loop
    }
    if (i == N_NODES) ptr[N_NODES] = N_EDGES;
}

// ---------------- counting-sort fill (1 edge/thread; src index only) ------------
__global__ void k_fill(const int* __restrict__ ei, int* fill,
                       int* __restrict__ csr_src) {
    int e = blockIdx.x * blockDim.x + threadIdx.x;
    if (e >= N_EDGES) return;
    int s = ei[e];
    int d = ei[N_EDGES + e];
    int pos = atomicAdd(&fill[d], 1);
    csr_src[pos] = s;
}

// ---------------- small GEMM: H[N, DOUT] = X[N, 64] @ W[64, DOUT], fp16 out -----
template <int DOUT>
__global__ void k_gemm(const float* __restrict__ X, const float* __restrict__ W,
                       __half* __restrict__ H) {
    constexpr int DIN  = 64;
    constexpr int C4   = DOUT / 4;         // 4-feature groups per row: 16 or 8
    constexpr int ROWS = 256 / C4;         // rows per block: 16 or 32
    constexpr int XS   = 17;               // padded row stride in float4
    __shared__ float4 sW[DIN * C4];        // W as [k][c4]
    __shared__ float4 sX4[ROWS * XS];

    int tid = threadIdx.x;
    for (int i = tid; i < DIN * C4; i += 256)
        sW[i] = ((const float4*)W)[i];

    int rowbase = blockIdx.x * ROWS;
    for (int i = tid; i < ROWS * (DIN / 4); i += 256) {
        int r = i / (DIN / 4);
        int q = i % (DIN / 4);
        int row = rowbase + r;
        sX4[r * XS + q] = (row < N_NODES)
            ? ((const float4*)X)[(size_t)row * (DIN / 4) + q]
            : make_float4(0.f, 0.f, 0.f, 0.f);
    }
    __syncthreads();

    int c4  = tid % C4;
    int r   = tid / C4;
    int row = rowbase + r;
    if (row >= N_NODES) return;

    const float* sx = (const float*)&sX4[r * XS];
    float4 acc = make_float4(0.f, 0.f, 0.f, 0.f);
#pragma unroll
    for (int k = 0; k < DIN; k++) {
        float  xv = sx[k];
        float4 wv = sW[k * C4 + c4];
        acc.x = fmaf(xv, wv.x, acc.x);
        acc.y = fmaf(xv, wv.y, acc.y);
        acc.z = fmaf(xv, wv.z, acc.z);
        acc.w = fmaf(xv, wv.w, acc.w);
    }
    __half2 p0 = __floats2half2_rn(acc.x, acc.y);
    __half2 p1 = __floats2half2_rn(acc.z, acc.w);
    uint2 u;
    u.x = *(unsigned*)&p0;
    u.y = *(unsigned*)&p1;
    ((uint2*)H)[(size_t)row * C4 + c4] = u;
}

// ---- fused pull aggregation + self-loop + bias + activation --------------------
// acc = Σ dinv[s]·h[s] (fp16 gather, fp32 accumulate)
// out = act(dinv[node]·(acc + dinv[node]·h[node]) + b)
template <int DOUT, bool TANH>
__global__ void k_agg(const int* __restrict__ ptr, const int* __restrict__ csr_src,
                      const __half* __restrict__ H, const float* __restrict__ dinv,
                      const float* __restrict__ b, float* __restrict__ OUT) {
    constexpr int C   = DOUT / 4;     // 16 (d=64) or 8 (d=32) lanes per node
    constexpr int NPB = 256 / C;      // nodes per block
    int lane = threadIdx.x % C;
    int node = blockIdx.x * NPB + threadIdx.x / C;
    if (node >= N_NODES) return;

    int beg = ptr[node];
    int end = ptr[node + 1];
    const uint2* H2 = (const uint2*)H;  // 4 halves per element; row stride = C

    float4 acc = make_float4(0.f, 0.f, 0.f, 0.f);

    auto fetch = [&](int s, float w) {
        uint2 u = H2[(size_t)s * C + lane];
        float2 f01 = __half22float2(*(__half2*)&u.x);
        float2 f23 = __half22float2(*(__half2*)&u.y);
        acc.x += f01.x * w;
        acc.y += f01.y * w;
        acc.z += f23.x * w;
        acc.w += f23.y * w;
    };

    int e = beg;
    for (; e + 3 < end; e += 4) {
        int   s0 = csr_src[e],     s1 = csr_src[e + 1];
        int   s2 = csr_src[e + 2], s3 = csr_src[e + 3];
        float w0 = dinv[s0],       w1 = dinv[s1];
        float w2 = dinv[s2],       w3 = dinv[s3];
        uint2 u0 = H2[(size_t)s0 * C + lane];
        uint2 u1 = H2[(size_t)s1 * C + lane];
        uint2 u2 = H2[(size_t)s2 * C + lane];
        uint2 u3 = H2[(size_t)s3 * C + lane];
        float2 a01 = __half22float2(*(__half2*)&u0.x), a23 = __half22float2(*(__half2*)&u0.y);
        float2 b01 = __half22float2(*(__half2*)&u1.x), b23 = __half22float2(*(__half2*)&u1.y);
        float2 c01 = __half22float2(*(__half2*)&u2.x), c23 = __half22float2(*(__half2*)&u2.y);
        float2 d01 = __half22float2(*(__half2*)&u3.x), d23 = __half22float2(*(__half2*)&u3.y);
        acc.x += a01.x * w0 + b01.x * w1 + c01.x * w2 + d01.x * w3;
        acc.y += a01.y * w0 + b01.y * w1 + c01.y * w2 + d01.y * w3;
        acc.z += a23.x * w0 + b23.x * w1 + c23.x * w2 + d23.x * w3;
        acc.w += a23.y * w0 + b23.y * w1 + c23.y * w2 + d23.y * w3;
    }
    for (; e < end; e++) fetch(csr_src[e], dinv[csr_src[e]]);

    float di = dinv[node];
    uint2 uh = H2[(size_t)node * C + lane];
    float2 h01 = __half22float2(*(__half2*)&uh.x);
    float2 h23 = __half22float2(*(__half2*)&uh.y);
    float4 bb = ((const float4*)b)[lane];
    float4 v;
    v.x = di * (acc.x + di * h01.x) + bb.x;
    v.y = di * (acc.y + di * h01.y) + bb.y;
    v.z = di * (acc.z + di * h23.x) + bb.z;
    v.w = di * (acc.w + di * h23.y) + bb.w;
    if (TANH) {
        v.x = tanhf(v.x); v.y = tanhf(v.y); v.z = tanhf(v.z); v.w = tanhf(v.w);
    }
    ((float4*)OUT)[(size_t)node * C + lane] = v;
}

// ---------------- launch --------------------------------------------------------
static inline int cdiv(long long a, int b) { return (int)((a + b - 1) / b); }

extern "C" void kernel_launch(void* const* d_in, const int* in_sizes, int n_in,
                              void* d_out, int out_size) {
    const float* x  = (const float*)d_in[0];
    const int*   ei = (const int*)d_in[1];      // JAX x64 disabled: int64 -> int32
    const float* W1 = (const float*)d_in[2];
    const float* b1 = (const float*)d_in[3];
    const float* W2 = (const float*)d_in[4];
    const float* b2 = (const float*)d_in[5];
    const float* W3 = (const float*)d_in[6];
    const float* b3 = (const float*)d_in[7];
    float*       out = (float*)d_out;

    float  *dinv, *x1, *x2;
    __half *h;
    int    *deg, *ptr, *fill, *bsum, *csr_src;
    cudaGetSymbolAddress((void**)&dinv,    g_dinv);
    cudaGetSymbolAddress((void**)&h,       g_h);
    cudaGetSymbolAddress((void**)&x1,      g_x1);
    cudaGetSymbolAddress((void**)&x2,      g_x2);
    cudaGetSymbolAddress((void**)&deg,     g_deg);
    cudaGetSymbolAddress((void**)&ptr,     g_ptr);
    cudaGetSymbolAddress((void**)&fill,    g_fill);
    cudaGetSymbolAddress((void**)&bsum,    g_bsum);
    cudaGetSymbolAddress((void**)&csr_src, g_csr_src);

    const int T = 256;

    // ---- CSR build + norm ----
    cudaMemsetAsync(deg, 0, N_NODES * sizeof(int));
    k_count_deg<<<cdiv(N_EDGES, T), T>>>(ei, deg);
    k_scanA    <<<NB_SCAN, T>>>(deg, bsum);
    k_scanC    <<<NB_SCAN, T>>>(deg, bsum, ptr, fill, dinv);
    k_fill     <<<cdiv(N_EDGES, T), T>>>(ei, fill, csr_src);

    // ---- layer 1: x -> x1 (tanh) ----
    k_gemm<64><<<cdiv(N_NODES, 16), T>>>(x, W1, h);
    k_agg<64, true><<<cdiv(N_NODES * 16, T), T>>>(ptr, csr_src, h, dinv, b1, x1);

    // ---- layer 2: x1 -> x2 (tanh) ----
    k_gemm<64><<<cdiv(N_NODES, 16), T>>>(x1, W2, h);
    k_agg<64, true><<<cdiv(N_NODES * 16, T), T>>>(ptr, csr_src, h, dinv, b2, x2);

    // ---- layer 3: x2 -> out (linear) ----
    k_gemm<32><<<cdiv(N_NODES, 32), T>>>(x2, W3, h);
    k_agg<32, false><<<cdiv(N_NODES * 8, T), T>>>(ptr, csr_src, h, dinv, b3, out);
}